// round 16
// baseline (speedup 1.0000x reference)
#include <cuda_runtime.h>
#include <cuda_bf16.h>
#include <cstdint>

// out[b,f] = input[b,f] * weight[f] + bias[nb_distrib, f]
// B=16384, F=4096, fp32. DRAM-bound stream, 3x reproduced at ~82us / 6.3-6.4 TB/s.
// Last lever under test (resubmit after infra failure): 256-bit global accesses
// (ld/st.global.v8.b32, sm_100+) -> half the LSU transactions, wider bursts at
// the saturated DRAM controller. Structured so only one weight/bias chunk is
// live at a time (regs ~52, keeps occupancy high -- R12 showed reg-pressure
// occ drops cost bandwidth).

static constexpr int F_DIM   = 4096;
static constexpr int F_VEC8  = F_DIM / 8;                 // 512 float8 per row
static constexpr unsigned TOTAL_VEC8 = 16384u * F_VEC8;   // 2^23 float8 chunks

struct f8 { float v[8]; };

__device__ __forceinline__ f8 ld_v8(const float* p) {
    uint32_t a,b,c,d,e,f,g,h;
    asm volatile("ld.global.v8.b32 {%0,%1,%2,%3,%4,%5,%6,%7}, [%8];"
                 : "=r"(a),"=r"(b),"=r"(c),"=r"(d),
                   "=r"(e),"=r"(f),"=r"(g),"=r"(h)
                 : "l"(p));
    f8 r;
    r.v[0]=__uint_as_float(a); r.v[1]=__uint_as_float(b);
    r.v[2]=__uint_as_float(c); r.v[3]=__uint_as_float(d);
    r.v[4]=__uint_as_float(e); r.v[5]=__uint_as_float(f);
    r.v[6]=__uint_as_float(g); r.v[7]=__uint_as_float(h);
    return r;
}

__device__ __forceinline__ void st_v8(float* p, const f8& r) {
    asm volatile("st.global.v8.b32 [%0], {%1,%2,%3,%4,%5,%6,%7,%8};"
                 :: "l"(p),
                    "r"(__float_as_uint(r.v[0])), "r"(__float_as_uint(r.v[1])),
                    "r"(__float_as_uint(r.v[2])), "r"(__float_as_uint(r.v[3])),
                    "r"(__float_as_uint(r.v[4])), "r"(__float_as_uint(r.v[5])),
                    "r"(__float_as_uint(r.v[6])), "r"(__float_as_uint(r.v[7]))
                 : "memory");
}

// Exact cover: 16384 blocks x 256 threads x 2 float8 = 2^23 chunks. No tail.
// Block strip == one row (512 float8), so weight/bias chunk indices are
// {tid, tid+256} in every block -> 32KB L2-resident, zero DRAM contribution.
__global__ __launch_bounds__(256)
void sharelinear_kernel(const float* __restrict__ in,
                        const float* __restrict__ weight,
                        const float* __restrict__ bias,
                        const int*   __restrict__ nb_distrib,
                        float*       __restrict__ out)
{
    const int nb = *nb_distrib;
    const float* __restrict__ brow = bias + (unsigned)nb * F_DIM;

    const unsigned tid   = threadIdx.x;
    const unsigned base8 = blockIdx.x * (256u * 2u) + tid;   // float8 index

    // Front-batch the two independent 256-bit input loads (2KB/warp in flight).
    f8 x0 = ld_v8(in + (size_t)(base8 + 0u * 256u) * 8u);
    f8 x1 = ld_v8(in + (size_t)(base8 + 1u * 256u) * 8u);

    const unsigned f0 = tid + 0u * 256u;   // strip is row-aligned
    const unsigned f1 = tid + 1u * 256u;

    // Chunk 0: load params, fma, store -- then chunk 1. Only one w/b pair
    // live at a time to bound register pressure.
    {
        f8 w = ld_v8(weight + (size_t)f0 * 8u);
        f8 b = ld_v8(brow   + (size_t)f0 * 8u);
        f8 r;
        #pragma unroll
        for (int i = 0; i < 8; i++) r.v[i] = fmaf(x0.v[i], w.v[i], b.v[i]);
        st_v8(out + (size_t)(base8 + 0u * 256u) * 8u, r);
    }
    {
        f8 w = ld_v8(weight + (size_t)f1 * 8u);
        f8 b = ld_v8(brow   + (size_t)f1 * 8u);
        f8 r;
        #pragma unroll
        for (int i = 0; i < 8; i++) r.v[i] = fmaf(x1.v[i], w.v[i], b.v[i]);
        st_v8(out + (size_t)(base8 + 1u * 256u) * 8u, r);
    }
}

extern "C" void kernel_launch(void* const* d_in, const int* in_sizes, int n_in,
                              void* d_out, int out_size)
{
    const float* in     = (const float*)d_in[0];   // input  [16384, 4096] f32
    const float* weight = (const float*)d_in[1];   // weight [4096]        f32
    const float* bias   = (const float*)d_in[2];   // bias   [1000, 4096]  f32
    const int*   nb     = (const int*)  d_in[3];   // nb_distrib scalar int32
    float*       out    = (float*)d_out;

    const int threads = 256;
    const int blocks  = (int)(TOTAL_VEC8 / (threads * 2));  // 16384, exact cover
    sharelinear_kernel<<<blocks, threads>>>(in, weight, bias, nb, out);
}

// round 17
// speedup vs baseline: 1.0178x; 1.0178x over previous
#include <cuda_runtime.h>
#include <cuda_bf16.h>

// out[b,f] = input[b,f] * weight[f] + bias[nb_distrib, f]
// B=16384, F=4096, fp32.
//
// ===== FINAL KERNEL (session verdict) =====
// Best of 4 structurally distinct variants, all probing the same wall:
//   float4/default 81.98us | float4/.cs 81.89-81.98us (3x reproduced)
//   persistent-grid 86.08us (occ regression) | float8-v8 82.46us (neutral)
// All well-shaped variants land at 6.27-6.41 TB/s = ~80% of 8 TB/s spec:
// the HBM3e mixed read/write turnaround ceiling for a 50/50 interleaved
// stream. Traffic is compulsory (268MB in + 268MB out; weight + selected
// bias row = 32KB, L2-resident). L2 39%, issue 7.6%, compute pipes idle.
// No kernel-side lever remains.
//
// Shape: exact-cover 16384 blocks x 256 threads x 4 float4 = 2^24, no tail.
// Block strip == one row -> param indices identical across blocks (L2 hits).
// 4 front-batched independent LDG.128 per thread (MLP_p1=4); 40 regs, occ 62%.

static constexpr int F_DIM   = 4096;
static constexpr int F_VEC   = F_DIM / 4;              // 1024 float4 per row
static constexpr unsigned TOTAL_VEC = 16384u * F_VEC;  // 2^24 float4

__global__ __launch_bounds__(256)
void sharelinear_kernel(const float4* __restrict__ in,
                        const float4* __restrict__ weight,
                        const float4* __restrict__ bias,
                        const int*    __restrict__ nb_distrib,
                        float4*       __restrict__ out)
{
    const int nb = *nb_distrib;
    const float4* __restrict__ brow = bias + (unsigned)nb * F_VEC;

    const unsigned base = blockIdx.x * (256u * 4u) + threadIdx.x;

    // 4 independent streaming (evict-first) 128-bit loads, front-batched.
    float4 x0 = __ldcs(in + base + 0u * 256u);
    float4 x1 = __ldcs(in + base + 1u * 256u);
    float4 x2 = __ldcs(in + base + 2u * 256u);
    float4 x3 = __ldcs(in + base + 3u * 256u);

    const unsigned f0 = threadIdx.x + 0u * 256u;   // strip is row-aligned
    const unsigned f1 = threadIdx.x + 1u * 256u;
    const unsigned f2 = threadIdx.x + 2u * 256u;
    const unsigned f3 = threadIdx.x + 3u * 256u;

    // Weight/bias: read-only, heavily reused -> NC/default path, L2-resident.
    float4 w0 = __ldg(weight + f0), b0 = __ldg(brow + f0);
    float4 w1 = __ldg(weight + f1), b1 = __ldg(brow + f1);
    float4 w2 = __ldg(weight + f2), b2 = __ldg(brow + f2);
    float4 w3 = __ldg(weight + f3), b3 = __ldg(brow + f3);

    float4 r0, r1, r2, r3;
    r0.x = fmaf(x0.x, w0.x, b0.x); r0.y = fmaf(x0.y, w0.y, b0.y);
    r0.z = fmaf(x0.z, w0.z, b0.z); r0.w = fmaf(x0.w, w0.w, b0.w);
    r1.x = fmaf(x1.x, w1.x, b1.x); r1.y = fmaf(x1.y, w1.y, b1.y);
    r1.z = fmaf(x1.z, w1.z, b1.z); r1.w = fmaf(x1.w, w1.w, b1.w);
    r2.x = fmaf(x2.x, w2.x, b2.x); r2.y = fmaf(x2.y, w2.y, b2.y);
    r2.z = fmaf(x2.z, w2.z, b2.z); r2.w = fmaf(x2.w, w2.w, b2.w);
    r3.x = fmaf(x3.x, w3.x, b3.x); r3.y = fmaf(x3.y, w3.y, b3.y);
    r3.z = fmaf(x3.z, w3.z, b3.z); r3.w = fmaf(x3.w, w3.w, b3.w);

    // Streaming stores: evict-first.
    __stcs(out + base + 0u * 256u, r0);
    __stcs(out + base + 1u * 256u, r1);
    __stcs(out + base + 2u * 256u, r2);
    __stcs(out + base + 3u * 256u, r3);
}

extern "C" void kernel_launch(void* const* d_in, const int* in_sizes, int n_in,
                              void* d_out, int out_size)
{
    const float4* in     = (const float4*)d_in[0];   // input  [16384, 4096] f32
    const float4* weight = (const float4*)d_in[1];   // weight [4096]        f32
    const float4* bias   = (const float4*)d_in[2];   // bias   [1000, 4096]  f32
    const int*    nb     = (const int*)   d_in[3];   // nb_distrib scalar int32
    float4*       out    = (float4*)d_out;

    const int threads = 256;
    const int blocks  = (int)(TOTAL_VEC / (threads * 4));   // 16384, exact cover
    sharelinear_kernel<<<blocks, threads>>>(in, weight, bias, nb, out);
}